// round 13
// baseline (speedup 1.0000x reference)
#include <cuda_runtime.h>
#include <cuda_bf16.h>
#include <cstdint>
#include <cstddef>

#define BB 3
#define DD 2048
#define HH 16
#define HDIM 128
#define KVH 2
#define FF 6144
#define VV 32000
#define TT 4096
#define TPAST 4095
#define NL 4
#define GQ (HH / KVH)   // 8
#define NCH 32
#define CT 128
#define CS (GQ * HDIM + 2 * GQ)   // 1040

__device__ float g_scratch[268800 + 1600000];

__device__ __forceinline__ uint32_t smem_u32(const void* p) {
    return (uint32_t)__cvta_generic_to_shared(p);
}
#define FMA2(acc, w, x) \
    asm("fma.rn.f32x2 %0, %1, %2, %0;" : "+l"(acc) : "l"(w), "l"(x))
#define PACK2(out, lo, hi) \
    asm("mov.b64 %0, {%1, %2};" : "=l"(out) : "f"(lo), "f"(hi))
#define UNPACK2(lo, hi, in) \
    asm("mov.b64 {%0, %1}, %2;" : "=f"(lo), "=f"(hi) : "l"(in))

// ---------------- rmsnorm ----------------
__global__ void k_rmsnorm(const float* __restrict__ x, const float* __restrict__ w,
                          float* __restrict__ y) {
    int b = blockIdx.x;
    const float* xb = x + b * DD;
    __shared__ float red[256];
    float ss = 0.f;
    for (int i = threadIdx.x; i < DD; i += 256) { float v = xb[i]; ss += v * v; }
    red[threadIdx.x] = ss;
    __syncthreads();
    for (int s = 128; s > 0; s >>= 1) {
        if (threadIdx.x < s) red[threadIdx.x] += red[threadIdx.x + s];
        __syncthreads();
    }
    float rs = rsqrtf(red[0] * (1.f / DD) + 1e-6f);
    for (int i = threadIdx.x; i < DD; i += 256) y[b * DD + i] = xb[i] * rs * w[i];
}

// ---------------- split-K GEMV, cp.async 6-stage ring + packed f32x2 math ----------------
template <int DC>
__global__ __launch_bounds__(128) void k_gemv_cp(
        const float* __restrict__ x,
        const float* __restrict__ xg, const float* __restrict__ xu, int xstride,
        const float* __restrict__ W0, int n0,
        const float* __restrict__ W1, int n1,
        const float* __restrict__ W2, int n2,
        int Ntot, float* __restrict__ part) {
    constexpr int SR = 8;
    constexpr int NS = 6;
    constexpr int STAGES = DC / SR;
    extern __shared__ float4 sm4[];
    float4* wt = sm4;                                           // [NS][SR][128] f4
    unsigned long long* xq = (unsigned long long*)(sm4 + NS * SR * 128); // [BB][DC] {v,v}

    int tid = threadIdx.x;
    int d0 = blockIdx.y * DC;
    int c4 = blockIdx.x * 128 + tid;
    int n = c4 * 4;
    bool active = n < Ntot;

    const float4* Wr = nullptr;
    size_t ld4 = 0;
    if (active) {
        const float* Wp; int c, ld;
        if (n < n0)            { Wp = W0; c = n;           ld = n0; }
        else if (n < n0 + n1)  { Wp = W1; c = n - n0;      ld = n1; }
        else                   { Wp = W2; c = n - n0 - n1; ld = n2; }
        Wr = reinterpret_cast<const float4*>(Wp + (size_t)d0 * ld) + (c >> 2);
        ld4 = (size_t)(ld >> 2);
    }

#pragma unroll
    for (int s = 0; s < NS - 1; ++s) {
        if (active) {
            float4* dst = wt + (s * SR) * 128 + tid;
            const float4* src = Wr + (size_t)(s * SR) * ld4;
#pragma unroll
            for (int r = 0; r < SR; ++r)
                asm volatile("cp.async.cg.shared.global [%0], [%1], 16;\n"
                             :: "r"(smem_u32(dst + r * 128)), "l"(src + r * ld4));
        }
        asm volatile("cp.async.commit_group;\n");
    }

    for (int i = tid; i < BB * DC; i += 128) {
        int b = i / DC, d = i - b * DC;
        float v;
        if (xg) {
            float g = xg[b * xstride + d0 + d];
            float u = xu[b * xstride + d0 + d];
            v = (g / (1.f + __expf(-g))) * u;
        } else {
            v = x[b * xstride + d0 + d];
        }
        unsigned long long p;
        PACK2(p, v, v);
        xq[i] = p;
    }
    __syncthreads();

    unsigned long long a0l = 0, a0h = 0, a1l = 0, a1h = 0, a2l = 0, a2h = 0;
    const ulonglong2* wt64 = (const ulonglong2*)wt;
    for (int s = 0; s < STAGES; ++s) {
        int sn = s + NS - 1;
        if (sn < STAGES && active) {
            float4* dst = wt + ((sn % NS) * SR) * 128 + tid;
            const float4* src = Wr + (size_t)(sn * SR) * ld4;
#pragma unroll
            for (int r = 0; r < SR; ++r)
                asm volatile("cp.async.cg.shared.global [%0], [%1], 16;\n"
                             :: "r"(smem_u32(dst + r * 128)), "l"(src + r * ld4));
        }
        asm volatile("cp.async.commit_group;\n");
        asm volatile("cp.async.wait_group 5;\n");
        int buf = s % NS;
        if (active) {
#pragma unroll
            for (int r = 0; r < SR; ++r) {
                ulonglong2 wv = wt64[(buf * SR + r) * 128 + tid];
                int d = s * SR + r;
                unsigned long long xx0 = xq[d];
                unsigned long long xx1 = xq[DC + d];
                unsigned long long xx2 = xq[2 * DC + d];
                FMA2(a0l, wv.x, xx0); FMA2(a0h, wv.y, xx0);
                FMA2(a1l, wv.x, xx1); FMA2(a1h, wv.y, xx1);
                FMA2(a2l, wv.x, xx2); FMA2(a2h, wv.y, xx2);
            }
        }
    }
    if (active) {
        float4 a0, a1, a2;
        UNPACK2(a0.x, a0.y, a0l); UNPACK2(a0.z, a0.w, a0h);
        UNPACK2(a1.x, a1.y, a1l); UNPACK2(a1.z, a1.w, a1h);
        UNPACK2(a2.x, a2.y, a2l); UNPACK2(a2.z, a2.w, a2h);
        float* P = part + (size_t)blockIdx.y * BB * Ntot;
        *(float4*)(P + 0 * (size_t)Ntot + n) = a0;
        *(float4*)(P + 1 * (size_t)Ntot + n) = a1;
        *(float4*)(P + 2 * (size_t)Ntot + n) = a2;
    }
}

// ---------------- reduce over splits (+residuals), float4, 4-way batched ----------------
__global__ void k_reduce(const float* __restrict__ part, int S, int Ntot,
                         const float* __restrict__ r1, const float* __restrict__ r2,
                         float* __restrict__ y) {
    int tot4 = BB * Ntot / 4;
    const float4* P4 = (const float4*)part;
    for (int i = blockIdx.x * 256 + threadIdx.x; i < tot4; i += gridDim.x * 256) {
        float4 a = {0,0,0,0};
        if (r1) a = ((const float4*)r1)[i];
        if (r2) { float4 t = ((const float4*)r2)[i]; a.x += t.x; a.y += t.y; a.z += t.z; a.w += t.w; }
        int s = 0;
        for (; s + 4 <= S; s += 4) {
            float4 p0 = P4[(size_t)(s + 0) * tot4 + i];
            float4 p1 = P4[(size_t)(s + 1) * tot4 + i];
            float4 p2 = P4[(size_t)(s + 2) * tot4 + i];
            float4 p3 = P4[(size_t)(s + 3) * tot4 + i];
            a.x += (p0.x + p1.x) + (p2.x + p3.x);
            a.y += (p0.y + p1.y) + (p2.y + p3.y);
            a.z += (p0.z + p1.z) + (p2.z + p3.z);
            a.w += (p0.w + p1.w) + (p2.w + p3.w);
        }
        for (; s < S; ++s) {
            float4 p = P4[(size_t)s * tot4 + i];
            a.x += p.x; a.y += p.y; a.z += p.z; a.w += p.w;
        }
        ((float4*)y)[i] = a;
    }
}

// ---------------- per-head RMSNorm + RoPE, fused QKV reduction (8 named accs) ----------------
#define LD8(base, stride, s0, r0,r1,r2,r3,r4,r5,r6,r7) \
    { r0 += base[(size_t)(s0+0)*(stride)]; r1 += base[(size_t)(s0+1)*(stride)]; \
      r2 += base[(size_t)(s0+2)*(stride)]; r3 += base[(size_t)(s0+3)*(stride)]; \
      r4 += base[(size_t)(s0+4)*(stride)]; r5 += base[(size_t)(s0+5)*(stride)]; \
      r6 += base[(size_t)(s0+6)*(stride)]; r7 += base[(size_t)(s0+7)*(stride)]; }

__global__ void k_rope(const float* __restrict__ part,
                       const float* __restrict__ wqn, const float* __restrict__ wkn,
                       const float* __restrict__ cq, const float* __restrict__ sq,
                       const float* __restrict__ ck, const float* __restrict__ sk,
                       float* __restrict__ qout, float* __restrict__ kcache,
                       float* __restrict__ vcache, int l) {
    __shared__ float nsh[HDIM];
    __shared__ float red[4];
    const int STR = BB * 2560;
    int t = threadIdx.x;
    int blk = blockIdx.x;
    const float scale = 0.29730177875068026f;  // 128^-0.25
    if (blk < BB * HH) {
        int b = blk / HH, h = blk % HH;
        const float* P = part + b * 2560 + h * HDIM + t;
        float r0=0,r1=0,r2=0,r3=0,r4=0,r5=0,r6=0,r7=0;
        LD8(P, STR, 0,  r0,r1,r2,r3,r4,r5,r6,r7);
        LD8(P, STR, 8,  r0,r1,r2,r3,r4,r5,r6,r7);
        LD8(P, STR, 16, r0,r1,r2,r3,r4,r5,r6,r7);
        LD8(P, STR, 24, r0,r1,r2,r3,r4,r5,r6,r7);
        float v = ((r0+r1)+(r2+r3)) + ((r4+r5)+(r6+r7));
        float ss = v * v;
        for (int o = 16; o; o >>= 1) ss += __shfl_xor_sync(0xffffffff, ss, o);
        if ((t & 31) == 0) red[t >> 5] = ss;
        __syncthreads();
        float tot = red[0] + red[1] + red[2] + red[3];
        float rs = rsqrtf(tot * (1.f / HDIM) + 1e-6f);
        float nv = v * rs * wqn[t] * scale;
        nsh[t] = nv;
        __syncthreads();
        float partner = (t < 64) ? -nsh[t + 64] : nsh[t - 64];
        qout[b * HH * HDIM + h * HDIM + t] = nv * cq[t] + partner * sq[t];
    } else {
        int j = blk - BB * HH;
        int b = j / KVH, kh = j % KVH;
        const float* Pk = part + b * 2560 + 2048 + kh * HDIM + t;
        const float* Pv = part + b * 2560 + 2304 + kh * HDIM + t;
        float k0=0,k1=0,k2=0,k3=0,k4=0,k5=0,k6=0,k7=0;
        float v0=0,v1=0,v2=0,v3=0,v4=0,v5=0,v6=0,v7=0;
        LD8(Pk, STR, 0,  k0,k1,k2,k3,k4,k5,k6,k7);
        LD8(Pv, STR, 0,  v0,v1,v2,v3,v4,v5,v6,v7);
        LD8(Pk, STR, 8,  k0,k1,k2,k3,k4,k5,k6,k7);
        LD8(Pv, STR, 8,  v0,v1,v2,v3,v4,v5,v6,v7);
        LD8(Pk, STR, 16, k0,k1,k2,k3,k4,k5,k6,k7);
        LD8(Pv, STR, 16, v0,v1,v2,v3,v4,v5,v6,v7);
        LD8(Pk, STR, 24, k0,k1,k2,k3,k4,k5,k6,k7);
        LD8(Pv, STR, 24, v0,v1,v2,v3,v4,v5,v6,v7);
        float v  = ((k0+k1)+(k2+k3)) + ((k4+k5)+(k6+k7));
        float vv = ((v0+v1)+(v2+v3)) + ((v4+v5)+(v6+v7));
        float ss = v * v;
        for (int o = 16; o; o >>= 1) ss += __shfl_xor_sync(0xffffffff, ss, o);
        if ((t & 31) == 0) red[t >> 5] = ss;
        __syncthreads();
        float tot = red[0] + red[1] + red[2] + red[3];
        float rs = rsqrtf(tot * (1.f / HDIM) + 1e-6f);
        float nv = v * rs * wkn[t] * scale;
        nsh[t] = nv;
        __syncthreads();
        float partner = (t < 64) ? -nsh[t + 64] : nsh[t - 64];
        float kval = nv * ck[t] + partner * sk[t];
        size_t kb = ((size_t)(l * BB + b) * KVH + kh) * (size_t)HDIM * TT;
        kcache[kb + (size_t)t * TT + TPAST] = kval;
        size_t vb = ((size_t)(l * BB + b) * KVH + kh) * (size_t)TT * HDIM;
        vcache[vb + (size_t)TPAST * HDIM + t] = vv;
    }
}

// ---------------- flash-decode attention partial ----------------
__global__ __launch_bounds__(256) void k_attn_part(
        const float* __restrict__ q, const float* __restrict__ kc,
        const float* __restrict__ vc, const float* __restrict__ ascale_p,
        float* __restrict__ po, int l) {
    extern __shared__ float smem[];
    float* tile = smem;
    float* qs   = smem + 16384;
    float* ps   = smem + 17408;
    int tid = threadIdx.x;
    int c = blockIdx.x;
    int by = blockIdx.y;
    int b = by / KVH, kh = by % KVH;
    int t0 = c * CT;
    float madd = -128.f * ascale_p[0];

    {
        float4 v = *(const float4*)(q + b * HH * HDIM + kh * GQ * HDIM + tid * 4);
        *(float4*)(qs + tid * 4) = v;
    }
    {
        const float* Kb = kc + (((size_t)(l * BB + b) * KVH + kh) * HDIM) * TT + t0;
        const float4* Ks = (const float4*)Kb;
        float4* Td = (float4*)tile;
        for (int i = tid; i < HDIM * CT / 4; i += 256) {
            int row = i >> 5, col = i & 31;
            Td[i] = __ldg(Ks + (size_t)row * (TT / 4) + col);
        }
    }
    __syncthreads();

    {
        int t = tid & 127, hb = tid >> 7;
        float a[4] = {0.f, 0.f, 0.f, 0.f};
        for (int d = 0; d < HDIM; ++d) {
            float kv = tile[d * CT + t];
#pragma unroll
            for (int g2 = 0; g2 < 4; ++g2)
                a[g2] += kv * qs[(hb * 4 + g2) * HDIM + d];
        }
        float mk = (t0 + t > 0) ? madd : 0.f;
#pragma unroll
        for (int g2 = 0; g2 < 4; ++g2)
            ps[(hb * 4 + g2) * CT + t] = a[g2] + mk;
    }
    __syncthreads();

    {
        int w = tid >> 5, lane = tid & 31;
        float mx = -1e30f;
        for (int j = lane; j < CT; j += 32) mx = fmaxf(mx, ps[w * CT + j]);
        for (int o = 16; o; o >>= 1) mx = fmaxf(mx, __shfl_xor_sync(0xffffffff, mx, o));
        float sum = 0.f;
        for (int j = lane; j < CT; j += 32) {
            float e = __expf(ps[w * CT + j] - mx);
            ps[w * CT + j] = e;
            sum += e;
        }
        for (int o = 16; o; o >>= 1) sum += __shfl_xor_sync(0xffffffff, sum, o);
        if (lane == 0) {
            float* rec = po + ((size_t)by * NCH + c) * CS;
            rec[GQ * HDIM + w] = mx;
            rec[GQ * HDIM + GQ + w] = sum;
        }
    }
    __syncthreads();

    {
        const float4* Vs = (const float4*)(vc +
            ((size_t)(l * BB + b) * KVH + kh) * (size_t)TT * HDIM + (size_t)t0 * HDIM);
        float4* Td = (float4*)tile;
        for (int i = tid; i < CT * HDIM / 4; i += 256) Td[i] = __ldg(Vs + i);
    }
    __syncthreads();

    {
        int d = tid & 127, hb = tid >> 7;
        float o[4] = {0.f, 0.f, 0.f, 0.f};
        for (int t = 0; t < CT; ++t) {
            float vv = tile[t * HDIM + d];
#pragma unroll
            for (int g2 = 0; g2 < 4; ++g2)
                o[g2] += vv * ps[(hb * 4 + g2) * CT + t];
        }
        float* rec = po + ((size_t)by * NCH + c) * CS;
#pragma unroll
        for (int g2 = 0; g2 < 4; ++g2)
            rec[(hb * 4 + g2) * HDIM + d] = o[g2];
    }
}

// ---------------- combine attention chunks ----------------
__global__ void k_attn_fin(const float* __restrict__ po, float* __restrict__ out) {
    int b = blockIdx.x / HH, h = blockIdx.x % HH;
    int kh = h >> 3, g = h & 7;
    int tid = threadIdx.x;
    const float* base = po + (size_t)(b * KVH + kh) * NCH * CS;
    float m = -1e30f;
#pragma unroll
    for (int c = 0; c < NCH; ++c) m = fmaxf(m, base[c * CS + GQ * HDIM + g]);
    float den = 0.f, acc = 0.f;
#pragma unroll 4
    for (int c = 0; c < NCH; ++c) {
        float mc = base[c * CS + GQ * HDIM + g];
        float lc = base[c * CS + GQ * HDIM + GQ + g];
        float w = __expf(mc - m);
        den += lc * w;
        acc += base[c * CS + g * HDIM + tid] * w;
    }
    out[b * HH * HDIM + h * HDIM + tid] = acc / den;
}

// ---------------- host ----------------
#define GEMV_SMEM(DC) (98304 + BB * (DC) * 8)

extern "C" void kernel_launch(void* const* d_in, const int* in_sizes, int n_in,
                              void* d_out, int out_size) {
    const float* hid   = (const float*)d_in[0];
    const float* pastk = (const float*)d_in[1];
    const float* pastv = (const float*)d_in[2];
    const float* deeps = (const float*)d_in[3];
    const float* cosq  = (const float*)d_in[4];
    const float* sinq  = (const float*)d_in[5];
    const float* cosk  = (const float*)d_in[6];
    const float* sink  = (const float*)d_in[7];
    const float* ascl  = (const float*)d_in[8];
    const float* w_in  = (const float*)d_in[9];
    const float* wq    = (const float*)d_in[10];
    const float* wk    = (const float*)d_in[11];
    const float* wv    = (const float*)d_in[12];
    const float* wqn   = (const float*)d_in[13];
    const float* wkn   = (const float*)d_in[14];
    const float* wo    = (const float*)d_in[15];
    const float* wpost = (const float*)d_in[16];
    const float* wgate = (const float*)d_in[17];
    const float* wup   = (const float*)d_in[18];
    const float* wdown = (const float*)d_in[19];
    const float* wfin  = (const float*)d_in[20];
    const float* wlm   = (const float*)d_in[21];

    float* out  = (float*)d_out;
    float* outk = out + BB * VV;
    float* outv = outk + (size_t)NL * BB * KVH * HDIM * TT;

    static float* sp = nullptr;
    if (!sp) {
        cudaGetSymbolAddress((void**)&sp, g_scratch);
        cudaFuncSetAttribute(k_attn_part, cudaFuncAttributeMaxDynamicSharedMemorySize,
                             73728);
        cudaFuncSetAttribute(k_gemv_cp<64>,  cudaFuncAttributeMaxDynamicSharedMemorySize, GEMV_SMEM(64));
        cudaFuncSetAttribute(k_gemv_cp<128>, cudaFuncAttributeMaxDynamicSharedMemorySize, GEMV_SMEM(128));
        cudaFuncSetAttribute(k_gemv_cp<192>, cudaFuncAttributeMaxDynamicSharedMemorySize, GEMV_SMEM(192));
        cudaFuncSetAttribute(k_gemv_cp<512>, cudaFuncAttributeMaxDynamicSharedMemorySize, GEMV_SMEM(512));
    }
    float* g_h     = sp;
    float* g_hn    = sp + 6144;
    float* g_q     = sp + 19968;
    float* g_attn  = sp + 26112;
    float* g_gu    = sp + 32256;
    float* g_apart = sp + 69120;
    float* g_part  = sp + 268800;

    // ---- KV copies via driver 2D copies (async, capture-legal) ----
    // K: 12288 rows of 4095 floats -> pitch-4096 rows
    cudaMemcpy2DAsync(outk, (size_t)TT * 4, pastk, (size_t)TPAST * 4,
                      (size_t)TPAST * 4, (size_t)NL * BB * KVH * HDIM,
                      cudaMemcpyDeviceToDevice, 0);
    // V: 24 chunks of 4095*128 floats -> pitch 4096*128 floats
    cudaMemcpy2DAsync(outv, (size_t)TT * HDIM * 4, pastv, (size_t)TPAST * HDIM * 4,
                      (size_t)TPAST * HDIM * 4, (size_t)NL * BB * KVH,
                      cudaMemcpyDeviceToDevice, 0);

    const float* hptr = hid;
    for (int l = 0; l < NL; ++l) {
        k_rmsnorm<<<BB, 256>>>(hptr, w_in + l * DD, g_hn);
        // QKV: 640 f4 cols -> 5 tiles; 32 splits of 64 (reduce fused into rope)
        k_gemv_cp<64><<<dim3(5, 32), 128, GEMV_SMEM(64)>>>(g_hn, nullptr, nullptr, DD,
            wq + (size_t)l * DD * 2048, 2048,
            wk + (size_t)l * DD * 256, 256,
            wv + (size_t)l * DD * 256, 256, 2560, g_part);

        k_rope<<<BB * HH + BB * KVH, 128>>>(g_part, wqn + l * HDIM, wkn + l * HDIM,
                                            cosq, sinq, cosk, sink,
                                            g_q, outk, outv, l);

        k_attn_part<<<dim3(NCH, BB * KVH), 256, 73728>>>(g_q, outk, outv, ascl,
                                                         g_apart, l);
        k_attn_fin<<<BB * HH, 128>>>(g_apart, g_attn);

        // wo: 512 f4 -> 4 tiles; 32 splits of 64
        k_gemv_cp<64><<<dim3(4, 32), 128, GEMV_SMEM(64)>>>(g_attn, nullptr, nullptr, DD,
            wo + (size_t)l * DD * DD, DD, nullptr, 0, nullptr, 0, DD, g_part);
        k_reduce<<<24, 256>>>(g_part, 32, DD, hptr, nullptr, g_h);

        k_rmsnorm<<<BB, 256>>>(g_h, wpost + l * DD, g_hn);
        // gate|up: 3072 f4 -> 24 tiles; 16 splits of 128
        k_gemv_cp<128><<<dim3(24, 16), 128, GEMV_SMEM(128)>>>(g_hn, nullptr, nullptr, DD,
            wgate + (size_t)l * DD * FF, FF,
            wup + (size_t)l * DD * FF, FF,
            nullptr, 0, 2 * FF, g_part);
        k_reduce<<<144, 256>>>(g_part, 16, 2 * FF, nullptr, nullptr, g_gu);

        // down (fused silu*up): 512 f4 -> 4 tiles; 32 splits of 192 over D=6144
        k_gemv_cp<192><<<dim3(4, 32), 128, GEMV_SMEM(192)>>>(nullptr, g_gu, g_gu + FF, 2 * FF,
            wdown + (size_t)l * FF * DD, DD, nullptr, 0, nullptr, 0, DD, g_part);
        const float* ds = (l < 3) ? (deeps + (size_t)l * BB * DD) : nullptr;
        k_reduce<<<24, 256>>>(g_part, 32, DD, g_h, ds, g_h);
        hptr = g_h;
    }

    k_rmsnorm<<<BB, 256>>>(g_h, wfin, g_hn);
    // lm_head: 8000 f4 -> 63 tiles; 4 splits of 512
    k_gemv_cp<512><<<dim3(63, 4), 128, GEMV_SMEM(512)>>>(g_hn, nullptr, nullptr, DD,
        wlm, VV, nullptr, 0, nullptr, 0, VV, g_part);
    k_reduce<<<375, 256>>>(g_part, 4, VV, nullptr, nullptr, out);
}

// round 14
// speedup vs baseline: 1.2841x; 1.2841x over previous
#include <cuda_runtime.h>
#include <cuda_bf16.h>
#include <cstdint>
#include <cstddef>

#define BB 3
#define DD 2048
#define HH 16
#define HDIM 128
#define KVH 2
#define FF 6144
#define VV 32000
#define TT 4096
#define TPAST 4095
#define NL 4
#define GQ (HH / KVH)   // 8
#define NCH 64          // attention chunks over T
#define CT 64           // tokens per chunk
#define CS (GQ * HDIM + 2 * GQ)   // 1040

__device__ float g_scratch[468480 + 1400000];

__device__ __forceinline__ uint32_t smem_u32(const void* p) {
    return (uint32_t)__cvta_generic_to_shared(p);
}
#define FMA2(acc, w, x) \
    asm("fma.rn.f32x2 %0, %1, %2, %0;" : "+l"(acc) : "l"(w), "l"(x))
#define PACK2(out, lo, hi) \
    asm("mov.b64 %0, {%1, %2};" : "=l"(out) : "f"(lo), "f"(hi))
#define UNPACK2(lo, hi, in) \
    asm("mov.b64 {%0, %1}, %2;" : "=f"(lo), "=f"(hi) : "l"(in))
#define CPA16(dst, src) \
    asm volatile("cp.async.cg.shared.global [%0], [%1], 16;\n" \
                 :: "r"(smem_u32(dst)), "l"(src))

// ---------------- rmsnorm ----------------
__global__ void k_rmsnorm(const float* __restrict__ x, const float* __restrict__ w,
                          float* __restrict__ y) {
    int b = blockIdx.x;
    const float* xb = x + b * DD;
    __shared__ float red[256];
    float ss = 0.f;
    for (int i = threadIdx.x; i < DD; i += 256) { float v = xb[i]; ss += v * v; }
    red[threadIdx.x] = ss;
    __syncthreads();
    for (int s = 128; s > 0; s >>= 1) {
        if (threadIdx.x < s) red[threadIdx.x] += red[threadIdx.x + s];
        __syncthreads();
    }
    float rs = rsqrtf(red[0] * (1.f / DD) + 1e-6f);
    for (int i = threadIdx.x; i < DD; i += 256) y[b * DD + i] = xb[i] * rs * w[i];
}

// ---------------- split-K GEMV, cp.async 6-stage ring + packed f32x2 math ----------------
template <int DC>
__global__ __launch_bounds__(128) void k_gemv_cp(
        const float* __restrict__ x,
        const float* __restrict__ xg, const float* __restrict__ xu, int xstride,
        const float* __restrict__ W0, int n0,
        const float* __restrict__ W1, int n1,
        const float* __restrict__ W2, int n2,
        int Ntot, float* __restrict__ part) {
    constexpr int SR = 8;
    constexpr int NS = 6;
    constexpr int STAGES = DC / SR;
    extern __shared__ float4 sm4[];
    float4* wt = sm4;                                           // [NS][SR][128] f4
    unsigned long long* xq = (unsigned long long*)(sm4 + NS * SR * 128); // [BB][DC] {v,v}

    int tid = threadIdx.x;
    int d0 = blockIdx.y * DC;
    int c4 = blockIdx.x * 128 + tid;
    int n = c4 * 4;
    bool active = n < Ntot;

    const float4* Wr = nullptr;
    size_t ld4 = 0;
    if (active) {
        const float* Wp; int c, ld;
        if (n < n0)            { Wp = W0; c = n;           ld = n0; }
        else if (n < n0 + n1)  { Wp = W1; c = n - n0;      ld = n1; }
        else                   { Wp = W2; c = n - n0 - n1; ld = n2; }
        Wr = reinterpret_cast<const float4*>(Wp + (size_t)d0 * ld) + (c >> 2);
        ld4 = (size_t)(ld >> 2);
    }

#pragma unroll
    for (int s = 0; s < NS - 1; ++s) {
        if (active) {
            float4* dst = wt + (s * SR) * 128 + tid;
            const float4* src = Wr + (size_t)(s * SR) * ld4;
#pragma unroll
            for (int r = 0; r < SR; ++r)
                CPA16(dst + r * 128, src + r * ld4);
        }
        asm volatile("cp.async.commit_group;\n");
    }

    for (int i = tid; i < BB * DC; i += 128) {
        int b = i / DC, d = i - b * DC;
        float v;
        if (xg) {
            float g = xg[b * xstride + d0 + d];
            float u = xu[b * xstride + d0 + d];
            v = (g / (1.f + __expf(-g))) * u;
        } else {
            v = x[b * xstride + d0 + d];
        }
        unsigned long long p;
        PACK2(p, v, v);
        xq[i] = p;
    }
    __syncthreads();

    unsigned long long a0l = 0, a0h = 0, a1l = 0, a1h = 0, a2l = 0, a2h = 0;
    const ulonglong2* wt64 = (const ulonglong2*)wt;
    for (int s = 0; s < STAGES; ++s) {
        int sn = s + NS - 1;
        if (sn < STAGES && active) {
            float4* dst = wt + ((sn % NS) * SR) * 128 + tid;
            const float4* src = Wr + (size_t)(sn * SR) * ld4;
#pragma unroll
            for (int r = 0; r < SR; ++r)
                CPA16(dst + r * 128, src + r * ld4);
        }
        asm volatile("cp.async.commit_group;\n");
        asm volatile("cp.async.wait_group 5;\n");
        int buf = s % NS;
        if (active) {
#pragma unroll
            for (int r = 0; r < SR; ++r) {
                ulonglong2 wv = wt64[(buf * SR + r) * 128 + tid];
                int d = s * SR + r;
                unsigned long long xx0 = xq[d];
                unsigned long long xx1 = xq[DC + d];
                unsigned long long xx2 = xq[2 * DC + d];
                FMA2(a0l, wv.x, xx0); FMA2(a0h, wv.y, xx0);
                FMA2(a1l, wv.x, xx1); FMA2(a1h, wv.y, xx1);
                FMA2(a2l, wv.x, xx2); FMA2(a2h, wv.y, xx2);
            }
        }
    }
    if (active) {
        float4 a0, a1, a2;
        UNPACK2(a0.x, a0.y, a0l); UNPACK2(a0.z, a0.w, a0h);
        UNPACK2(a1.x, a1.y, a1l); UNPACK2(a1.z, a1.w, a1h);
        UNPACK2(a2.x, a2.y, a2l); UNPACK2(a2.z, a2.w, a2h);
        float* P = part + (size_t)blockIdx.y * BB * Ntot;
        *(float4*)(P + 0 * (size_t)Ntot + n) = a0;
        *(float4*)(P + 1 * (size_t)Ntot + n) = a1;
        *(float4*)(P + 2 * (size_t)Ntot + n) = a2;
    }
}

// ---------------- reduce over splits (+residuals), float4 ----------------
__global__ void k_reduce(const float* __restrict__ part, int S, int Ntot,
                         const float* __restrict__ r1, const float* __restrict__ r2,
                         float* __restrict__ y) {
    int tot4 = BB * Ntot / 4;
    const float4* P4 = (const float4*)part;
    for (int i = blockIdx.x * 256 + threadIdx.x; i < tot4; i += gridDim.x * 256) {
        float4 a = {0,0,0,0};
        if (r1) a = ((const float4*)r1)[i];
        if (r2) { float4 t = ((const float4*)r2)[i]; a.x += t.x; a.y += t.y; a.z += t.z; a.w += t.w; }
        for (int s = 0; s < S; ++s) {
            float4 p = P4[(size_t)s * tot4 + i];
            a.x += p.x; a.y += p.y; a.z += p.z; a.w += p.w;
        }
        ((float4*)y)[i] = a;
    }
}

// ---------------- per-head RMSNorm + RoPE, fused QKV split-reduction ----------------
__global__ void k_rope(const float* __restrict__ part, int S,
                       const float* __restrict__ wqn, const float* __restrict__ wkn,
                       const float* __restrict__ cq, const float* __restrict__ sq,
                       const float* __restrict__ ck, const float* __restrict__ sk,
                       float* __restrict__ qout, float* __restrict__ kcache,
                       float* __restrict__ vcache, int l) {
    __shared__ float nsh[HDIM];
    __shared__ float red[4];
    int t = threadIdx.x;
    int blk = blockIdx.x;
    const float scale = 0.29730177875068026f;  // 128^-0.25
    if (blk < BB * HH) {
        int b = blk / HH, h = blk % HH;
        const float* P = part + b * 2560 + h * HDIM + t;
        float v = 0.f;
        for (int s = 0; s < S; ++s) v += P[(size_t)s * BB * 2560];
        float ss = v * v;
        for (int o = 16; o; o >>= 1) ss += __shfl_xor_sync(0xffffffff, ss, o);
        if ((t & 31) == 0) red[t >> 5] = ss;
        __syncthreads();
        float tot = red[0] + red[1] + red[2] + red[3];
        float rs = rsqrtf(tot * (1.f / HDIM) + 1e-6f);
        float nv = v * rs * wqn[t] * scale;
        nsh[t] = nv;
        __syncthreads();
        float partner = (t < 64) ? -nsh[t + 64] : nsh[t - 64];
        qout[b * HH * HDIM + h * HDIM + t] = nv * cq[t] + partner * sq[t];
    } else {
        int j = blk - BB * HH;
        int b = j / KVH, kh = j % KVH;
        const float* Pk = part + b * 2560 + 2048 + kh * HDIM + t;
        const float* Pv = part + b * 2560 + 2304 + kh * HDIM + t;
        float v = 0.f, vv = 0.f;
        for (int s = 0; s < S; ++s) {
            v  += Pk[(size_t)s * BB * 2560];
            vv += Pv[(size_t)s * BB * 2560];
        }
        float ss = v * v;
        for (int o = 16; o; o >>= 1) ss += __shfl_xor_sync(0xffffffff, ss, o);
        if ((t & 31) == 0) red[t >> 5] = ss;
        __syncthreads();
        float tot = red[0] + red[1] + red[2] + red[3];
        float rs = rsqrtf(tot * (1.f / HDIM) + 1e-6f);
        float nv = v * rs * wkn[t] * scale;
        nsh[t] = nv;
        __syncthreads();
        float partner = (t < 64) ? -nsh[t + 64] : nsh[t - 64];
        float kval = nv * ck[t] + partner * sk[t];
        size_t kb = ((size_t)(l * BB + b) * KVH + kh) * (size_t)HDIM * TT;
        kcache[kb + (size_t)t * TT + TPAST] = kval;
        size_t vb = ((size_t)(l * BB + b) * KVH + kh) * (size_t)TT * HDIM;
        vcache[vb + (size_t)TPAST * HDIM + t] = vv;
    }
}

// ---------------- flash-decode attention partial, cp.async overlapped ----------------
// smem: Kt[CT*HDIM] | Vt[CT*HDIM] | qs[1024] | ps[GQ*CT]  (CT=64 -> 71.7 KB)
__global__ __launch_bounds__(256) void k_attn_part(
        const float* __restrict__ q, const float* __restrict__ kc,
        const float* __restrict__ vc, const float* __restrict__ ascale_p,
        float* __restrict__ po, int l) {
    extern __shared__ float smem[];
    float4* Kt = (float4*)smem;                  // 2048 f4
    float4* Vt = (float4*)(smem + CT * HDIM);    // 2048 f4
    float* qs  = smem + 2 * CT * HDIM;           // 1024
    float* ps  = qs + GQ * HDIM;                 // 512
    int tid = threadIdx.x;
    int c = blockIdx.x;
    int by = blockIdx.y;
    int b = by / KVH, kh = by % KVH;
    int t0 = c * CT;
    float madd = -128.f * ascale_p[0];

    // issue K tile cp.async: [d][t] layout, 16 f4 per row
    {
        const float4* Ks = (const float4*)(kc +
            (((size_t)(l * BB + b) * KVH + kh) * HDIM) * TT + t0);
#pragma unroll
        for (int it = 0; it < HDIM * CT / 4 / 256; ++it) {
            int i = it * 256 + tid;
            int row = i >> 4, col = i & 15;
            CPA16(Kt + i, Ks + (size_t)row * (TT / 4) + col);
        }
    }
    asm volatile("cp.async.commit_group;\n");

    // stage q (regular loads, overlapped with K in flight)
    {
        float4 v = *(const float4*)(q + b * HH * HDIM + kh * GQ * HDIM + tid * 4);
        *(float4*)(qs + tid * 4) = v;
    }

    // issue V tile cp.async (contiguous 32 KB)
    {
        const float4* Vs = (const float4*)(vc +
            ((size_t)(l * BB + b) * KVH + kh) * (size_t)TT * HDIM + (size_t)t0 * HDIM);
#pragma unroll
        for (int it = 0; it < CT * HDIM / 4 / 256; ++it) {
            int i = it * 256 + tid;
            CPA16(Vt + i, Vs + i);
        }
    }
    asm volatile("cp.async.commit_group;\n");

    asm volatile("cp.async.wait_group 1;\n");   // K tile complete; V still in flight
    __syncthreads();

    // scores: t = tid&63 token, hg = tid>>6 handles heads hg*2, hg*2+1
    {
        int t = tid & 63, hg = tid >> 6;
        const float* tileK = (const float*)Kt;
        float a0 = 0.f, a1 = 0.f;
        const float* q0 = qs + (hg * 2) * HDIM;
        const float* q1 = qs + (hg * 2 + 1) * HDIM;
        for (int d = 0; d < HDIM; ++d) {
            float kv = tileK[d * CT + t];
            a0 += kv * q0[d];
            a1 += kv * q1[d];
        }
        float mk = (t0 + t > 0) ? madd : 0.f;
        ps[(hg * 2) * CT + t] = a0 + mk;
        ps[(hg * 2 + 1) * CT + t] = a1 + mk;
    }
    __syncthreads();

    // per-head local max & exp-sum (warp w = head w; 2 elements per lane)
    {
        int w = tid >> 5, lane = tid & 31;
        float e0 = ps[w * CT + lane], e1 = ps[w * CT + lane + 32];
        float mx = fmaxf(e0, e1);
        for (int o = 16; o; o >>= 1) mx = fmaxf(mx, __shfl_xor_sync(0xffffffff, mx, o));
        e0 = __expf(e0 - mx); e1 = __expf(e1 - mx);
        ps[w * CT + lane] = e0; ps[w * CT + lane + 32] = e1;
        float sum = e0 + e1;
        for (int o = 16; o; o >>= 1) sum += __shfl_xor_sync(0xffffffff, sum, o);
        if (lane == 0) {
            float* rec = po + ((size_t)by * NCH + c) * CS;
            rec[GQ * HDIM + w] = mx;
            rec[GQ * HDIM + GQ + w] = sum;
        }
    }

    asm volatile("cp.async.wait_group 0;\n");   // V tile complete
    __syncthreads();

    // output: d = tid&127, hb = tid>>7 -> heads hb*4..hb*4+3
    {
        int d = tid & 127, hb = tid >> 7;
        const float* tileV = (const float*)Vt;
        float o[4] = {0.f, 0.f, 0.f, 0.f};
        for (int t = 0; t < CT; ++t) {
            float vv = tileV[t * HDIM + d];
#pragma unroll
            for (int g2 = 0; g2 < 4; ++g2)
                o[g2] += vv * ps[(hb * 4 + g2) * CT + t];
        }
        float* rec = po + ((size_t)by * NCH + c) * CS;
#pragma unroll
        for (int g2 = 0; g2 < 4; ++g2)
            rec[(hb * 4 + g2) * HDIM + d] = o[g2];
    }
}

// ---------------- combine attention chunks ----------------
__global__ void k_attn_fin(const float* __restrict__ po, float* __restrict__ out) {
    int b = blockIdx.x / HH, h = blockIdx.x % HH;
    int kh = h >> 3, g = h & 7;
    int tid = threadIdx.x;
    const float* base = po + (size_t)(b * KVH + kh) * NCH * CS;
    float m = -1e30f;
    for (int c = 0; c < NCH; ++c) m = fmaxf(m, base[c * CS + GQ * HDIM + g]);
    float den = 0.f, acc = 0.f;
    for (int c = 0; c < NCH; ++c) {
        float mc = base[c * CS + GQ * HDIM + g];
        float lc = base[c * CS + GQ * HDIM + GQ + g];
        float w = __expf(mc - m);
        den += lc * w;
        acc += base[c * CS + g * HDIM + tid] * w;
    }
    out[b * HH * HDIM + h * HDIM + tid] = acc / den;
}

// ---------------- past-cache copies (merged, kernel path) ----------------
#define KROWS (NL * BB * KVH * HDIM)             // 12288 K rows
#define VPER  (TPAST * HDIM / 4)                 // 131040 float4 per (l,b,kh)
#define VBLKS ((NL * BB * KVH * VPER + 255) / 256)
__global__ void k_copy_kv(const float* __restrict__ pk, float* __restrict__ outk,
                          const float4* __restrict__ pv, float4* __restrict__ outv) {
    int blk = blockIdx.x;
    if (blk < KROWS) {
        const float* src = pk + (size_t)blk * TPAST;
        float* dst = outk + (size_t)blk * TT;
        int t = threadIdx.x;
#pragma unroll 4
        for (int i = 0; i < 16; ++i) {
            int idx = i * 256 + t;
            if (idx < TPAST) dst[idx] = __ldg(src + idx);
        }
    } else {
        long long i = (long long)(blk - KROWS) * 256 + threadIdx.x;
        if (i < (long long)NL * BB * KVH * VPER) {
            int ch = (int)(i / VPER);
            int rem = (int)(i - (long long)ch * VPER);
            outv[(size_t)ch * (TT * HDIM / 4) + rem] = __ldg(pv + (size_t)ch * VPER + rem);
        }
    }
}

// ---------------- host ----------------
#define GEMV_SMEM(DC) (98304 + BB * (DC) * 8)
#define ATTN_SMEM ((2 * CT * HDIM + GQ * HDIM + GQ * CT) * 4)

extern "C" void kernel_launch(void* const* d_in, const int* in_sizes, int n_in,
                              void* d_out, int out_size) {
    const float* hid   = (const float*)d_in[0];
    const float* pastk = (const float*)d_in[1];
    const float* pastv = (const float*)d_in[2];
    const float* deeps = (const float*)d_in[3];
    const float* cosq  = (const float*)d_in[4];
    const float* sinq  = (const float*)d_in[5];
    const float* cosk  = (const float*)d_in[6];
    const float* sink  = (const float*)d_in[7];
    const float* ascl  = (const float*)d_in[8];
    const float* w_in  = (const float*)d_in[9];
    const float* wq    = (const float*)d_in[10];
    const float* wk    = (const float*)d_in[11];
    const float* wv    = (const float*)d_in[12];
    const float* wqn   = (const float*)d_in[13];
    const float* wkn   = (const float*)d_in[14];
    const float* wo    = (const float*)d_in[15];
    const float* wpost = (const float*)d_in[16];
    const float* wgate = (const float*)d_in[17];
    const float* wup   = (const float*)d_in[18];
    const float* wdown = (const float*)d_in[19];
    const float* wfin  = (const float*)d_in[20];
    const float* wlm   = (const float*)d_in[21];

    float* out  = (float*)d_out;
    float* outk = out + BB * VV;
    float* outv = outk + (size_t)NL * BB * KVH * HDIM * TT;

    static float* sp = nullptr;
    if (!sp) {
        cudaGetSymbolAddress((void**)&sp, g_scratch);
        cudaFuncSetAttribute(k_attn_part, cudaFuncAttributeMaxDynamicSharedMemorySize,
                             ATTN_SMEM);
        cudaFuncSetAttribute(k_gemv_cp<64>,  cudaFuncAttributeMaxDynamicSharedMemorySize, GEMV_SMEM(64));
        cudaFuncSetAttribute(k_gemv_cp<128>, cudaFuncAttributeMaxDynamicSharedMemorySize, GEMV_SMEM(128));
        cudaFuncSetAttribute(k_gemv_cp<192>, cudaFuncAttributeMaxDynamicSharedMemorySize, GEMV_SMEM(192));
        cudaFuncSetAttribute(k_gemv_cp<512>, cudaFuncAttributeMaxDynamicSharedMemorySize, GEMV_SMEM(512));
    }
    float* g_h     = sp;
    float* g_hn    = sp + 6144;
    float* g_q     = sp + 19968;
    float* g_attn  = sp + 26112;
    float* g_gu    = sp + 32256;
    float* g_apart = sp + 69120;     // BB*KVH*NCH*CS = 399360 floats
    float* g_part  = sp + 468480;

    k_copy_kv<<<KROWS + VBLKS, 256>>>(pastk, outk, (const float4*)pastv, (float4*)outv);

    const float* hptr = hid;
    for (int l = 0; l < NL; ++l) {
        k_rmsnorm<<<BB, 256>>>(hptr, w_in + l * DD, g_hn);
        // QKV: 640 f4 cols -> 5 tiles; 32 splits of 64 (reduce fused into rope)
        k_gemv_cp<64><<<dim3(5, 32), 128, GEMV_SMEM(64)>>>(g_hn, nullptr, nullptr, DD,
            wq + (size_t)l * DD * 2048, 2048,
            wk + (size_t)l * DD * 256, 256,
            wv + (size_t)l * DD * 256, 256, 2560, g_part);

        k_rope<<<BB * HH + BB * KVH, 128>>>(g_part, 32, wqn + l * HDIM, wkn + l * HDIM,
                                            cosq, sinq, cosk, sink,
                                            g_q, outk, outv, l);

        k_attn_part<<<dim3(NCH, BB * KVH), 256, ATTN_SMEM>>>(g_q, outk, outv, ascl,
                                                             g_apart, l);
        k_attn_fin<<<BB * HH, 128>>>(g_apart, g_attn);

        // wo: 512 f4 -> 4 tiles; 32 splits of 64
        k_gemv_cp<64><<<dim3(4, 32), 128, GEMV_SMEM(64)>>>(g_attn, nullptr, nullptr, DD,
            wo + (size_t)l * DD * DD, DD, nullptr, 0, nullptr, 0, DD, g_part);
        k_reduce<<<24, 256>>>(g_part, 32, DD, hptr, nullptr, g_h);

        k_rmsnorm<<<BB, 256>>>(g_h, wpost + l * DD, g_hn);
        // gate|up: 3072 f4 -> 24 tiles; 16 splits of 128
        k_gemv_cp<128><<<dim3(24, 16), 128, GEMV_SMEM(128)>>>(g_hn, nullptr, nullptr, DD,
            wgate + (size_t)l * DD * FF, FF,
            wup + (size_t)l * DD * FF, FF,
            nullptr, 0, 2 * FF, g_part);
        k_reduce<<<144, 256>>>(g_part, 16, 2 * FF, nullptr, nullptr, g_gu);

        // down (fused silu*up): 512 f4 -> 4 tiles; 32 splits of 192 over D=6144
        k_gemv_cp<192><<<dim3(4, 32), 128, GEMV_SMEM(192)>>>(nullptr, g_gu, g_gu + FF, 2 * FF,
            wdown + (size_t)l * FF * DD, DD, nullptr, 0, nullptr, 0, DD, g_part);
        const float* ds = (l < 3) ? (deeps + (size_t)l * BB * DD) : nullptr;
        k_reduce<<<24, 256>>>(g_part, 32, DD, g_h, ds, g_h);
        hptr = g_h;
    }

    k_rmsnorm<<<BB, 256>>>(g_h, wfin, g_hn);
    // lm_head: 8000 f4 -> 63 tiles; 4 splits of 512
    k_gemv_cp<512><<<dim3(63, 4), 128, GEMV_SMEM(512)>>>(g_hn, nullptr, nullptr, DD,
        wlm, VV, nullptr, 0, nullptr, 0, VV, g_part);
    k_reduce<<<375, 256>>>(g_part, 4, VV, nullptr, nullptr, out);
}

// round 15
// speedup vs baseline: 1.3167x; 1.0254x over previous
#include <cuda_runtime.h>
#include <cuda_bf16.h>
#include <cstdint>
#include <cstddef>

#define BB 3
#define DD 2048
#define HH 16
#define HDIM 128
#define KVH 2
#define FF 6144
#define VV 32000
#define TT 4096
#define TPAST 4095
#define NL 4
#define GQ (HH / KVH)   // 8
#define NCH 64          // attention chunks over T
#define CT 64           // tokens per chunk
#define CS (GQ * HDIM + 2 * GQ)   // 1040

__device__ float g_scratch[468480 + 1400000];

__device__ __forceinline__ uint32_t smem_u32(const void* p) {
    return (uint32_t)__cvta_generic_to_shared(p);
}
#define FMA2(acc, w, x) \
    asm("fma.rn.f32x2 %0, %1, %2, %0;" : "+l"(acc) : "l"(w), "l"(x))
#define PACK2(out, lo, hi) \
    asm("mov.b64 %0, {%1, %2};" : "=l"(out) : "f"(lo), "f"(hi))
#define UNPACK2(lo, hi, in) \
    asm("mov.b64 {%0, %1}, %2;" : "=f"(lo), "=f"(hi) : "l"(in))
#define CPA16(dst, src) \
    asm volatile("cp.async.cg.shared.global [%0], [%1], 16;\n" \
                 :: "r"(smem_u32(dst)), "l"(src))

// ---------------- rmsnorm ----------------
__global__ void k_rmsnorm(const float* __restrict__ x, const float* __restrict__ w,
                          float* __restrict__ y) {
    int b = blockIdx.x;
    const float* xb = x + b * DD;
    __shared__ float red[256];
    float ss = 0.f;
    for (int i = threadIdx.x; i < DD; i += 256) { float v = xb[i]; ss += v * v; }
    red[threadIdx.x] = ss;
    __syncthreads();
    for (int s = 128; s > 0; s >>= 1) {
        if (threadIdx.x < s) red[threadIdx.x] += red[threadIdx.x + s];
        __syncthreads();
    }
    float rs = rsqrtf(red[0] * (1.f / DD) + 1e-6f);
    for (int i = threadIdx.x; i < DD; i += 256) y[b * DD + i] = xb[i] * rs * w[i];
}

// ---------------- split-K GEMV, cp.async 6-stage ring + packed f32x2 math ----------------
template <int DC>
__global__ __launch_bounds__(128) void k_gemv_cp(
        const float* __restrict__ x,
        const float* __restrict__ xg, const float* __restrict__ xu, int xstride,
        const float* __restrict__ W0, int n0,
        const float* __restrict__ W1, int n1,
        const float* __restrict__ W2, int n2,
        int Ntot, float* __restrict__ part) {
    constexpr int SR = 8;
    constexpr int NS = 6;
    constexpr int STAGES = DC / SR;
    extern __shared__ float4 sm4[];
    float4* wt = sm4;                                           // [NS][SR][128] f4
    unsigned long long* xq = (unsigned long long*)(sm4 + NS * SR * 128); // [BB][DC] {v,v}

    int tid = threadIdx.x;
    int d0 = blockIdx.y * DC;
    int c4 = blockIdx.x * 128 + tid;
    int n = c4 * 4;
    bool active = n < Ntot;

    const float4* Wr = nullptr;
    size_t ld4 = 0;
    if (active) {
        const float* Wp; int c, ld;
        if (n < n0)            { Wp = W0; c = n;           ld = n0; }
        else if (n < n0 + n1)  { Wp = W1; c = n - n0;      ld = n1; }
        else                   { Wp = W2; c = n - n0 - n1; ld = n2; }
        Wr = reinterpret_cast<const float4*>(Wp + (size_t)d0 * ld) + (c >> 2);
        ld4 = (size_t)(ld >> 2);
    }

#pragma unroll
    for (int s = 0; s < NS - 1; ++s) {
        if (active) {
            float4* dst = wt + (s * SR) * 128 + tid;
            const float4* src = Wr + (size_t)(s * SR) * ld4;
#pragma unroll
            for (int r = 0; r < SR; ++r)
                CPA16(dst + r * 128, src + r * ld4);
        }
        asm volatile("cp.async.commit_group;\n");
    }

    for (int i = tid; i < BB * DC; i += 128) {
        int b = i / DC, d = i - b * DC;
        float v;
        if (xg) {
            float g = xg[b * xstride + d0 + d];
            float u = xu[b * xstride + d0 + d];
            v = (g / (1.f + __expf(-g))) * u;
        } else {
            v = x[b * xstride + d0 + d];
        }
        unsigned long long p;
        PACK2(p, v, v);
        xq[i] = p;
    }
    __syncthreads();

    unsigned long long a0l = 0, a0h = 0, a1l = 0, a1h = 0, a2l = 0, a2h = 0;
    const ulonglong2* wt64 = (const ulonglong2*)wt;
    for (int s = 0; s < STAGES; ++s) {
        int sn = s + NS - 1;
        if (sn < STAGES && active) {
            float4* dst = wt + ((sn % NS) * SR) * 128 + tid;
            const float4* src = Wr + (size_t)(sn * SR) * ld4;
#pragma unroll
            for (int r = 0; r < SR; ++r)
                CPA16(dst + r * 128, src + r * ld4);
        }
        asm volatile("cp.async.commit_group;\n");
        asm volatile("cp.async.wait_group 5;\n");
        int buf = s % NS;
        if (active) {
#pragma unroll
            for (int r = 0; r < SR; ++r) {
                ulonglong2 wv = wt64[(buf * SR + r) * 128 + tid];
                int d = s * SR + r;
                unsigned long long xx0 = xq[d];
                unsigned long long xx1 = xq[DC + d];
                unsigned long long xx2 = xq[2 * DC + d];
                FMA2(a0l, wv.x, xx0); FMA2(a0h, wv.y, xx0);
                FMA2(a1l, wv.x, xx1); FMA2(a1h, wv.y, xx1);
                FMA2(a2l, wv.x, xx2); FMA2(a2h, wv.y, xx2);
            }
        }
    }
    if (active) {
        float4 a0, a1, a2;
        UNPACK2(a0.x, a0.y, a0l); UNPACK2(a0.z, a0.w, a0h);
        UNPACK2(a1.x, a1.y, a1l); UNPACK2(a1.z, a1.w, a1h);
        UNPACK2(a2.x, a2.y, a2l); UNPACK2(a2.z, a2.w, a2h);
        float* P = part + (size_t)blockIdx.y * BB * Ntot;
        *(float4*)(P + 0 * (size_t)Ntot + n) = a0;
        *(float4*)(P + 1 * (size_t)Ntot + n) = a1;
        *(float4*)(P + 2 * (size_t)Ntot + n) = a2;
    }
}

// ---------------- reduce: 4 thread-groups over splits, smem combine ----------------
__global__ void k_reduce(const float* __restrict__ part, int S, int Ntot,
                         const float* __restrict__ r1, const float* __restrict__ r2,
                         float* __restrict__ y) {
    __shared__ float4 sh[4][64];
    int sg = threadIdx.x >> 6;        // split group 0..3
    int t  = threadIdx.x & 63;
    int tot4 = BB * Ntot / 4;
    const float4* P4 = (const float4*)part;
    for (int base = blockIdx.x * 64; base < tot4; base += gridDim.x * 64) {
        int i = base + t;
        float4 a = {0, 0, 0, 0};
        if (i < tot4) {
            for (int s = sg; s < S; s += 4) {
                float4 p = P4[(size_t)s * tot4 + i];
                a.x += p.x; a.y += p.y; a.z += p.z; a.w += p.w;
            }
        }
        sh[sg][t] = a;
        __syncthreads();
        if (sg == 0 && i < tot4) {
            float4 b1 = sh[1][t], b2 = sh[2][t], b3 = sh[3][t];
            a.x = (a.x + b1.x) + (b2.x + b3.x);
            a.y = (a.y + b1.y) + (b2.y + b3.y);
            a.z = (a.z + b1.z) + (b2.z + b3.z);
            a.w = (a.w + b1.w) + (b2.w + b3.w);
            if (r1) { float4 r = ((const float4*)r1)[i]; a.x += r.x; a.y += r.y; a.z += r.z; a.w += r.w; }
            if (r2) { float4 r = ((const float4*)r2)[i]; a.x += r.x; a.y += r.y; a.z += r.z; a.w += r.w; }
            ((float4*)y)[i] = a;
        }
        __syncthreads();
    }
}

// ---------------- per-head RMSNorm + RoPE, fused QKV reduction (4 thread-groups) ----------------
// 512 threads = 4 groups x 128; group g sums splits {g, g+4, ..., g+28}
__global__ __launch_bounds__(512) void k_rope(
        const float* __restrict__ part, int S,
        const float* __restrict__ wqn, const float* __restrict__ wkn,
        const float* __restrict__ cq, const float* __restrict__ sq,
        const float* __restrict__ ck, const float* __restrict__ sk,
        float* __restrict__ qout, float* __restrict__ kcache,
        float* __restrict__ vcache, int l) {
    __shared__ float shk[4][HDIM];
    __shared__ float shv[4][HDIM];
    __shared__ float nsh[HDIM];
    __shared__ float red[4];
    int tid = threadIdx.x;
    int g = tid >> 7, t = tid & 127;
    int blk = blockIdx.x;
    const float scale = 0.29730177875068026f;  // 128^-0.25
    const size_t STR = (size_t)BB * 2560;

    if (blk < BB * HH) {
        int b = blk / HH, h = blk % HH;
        const float* P = part + b * 2560 + h * HDIM + t;
        float a = 0.f;
        for (int s = g; s < S; s += 4) a += P[s * STR];
        shk[g][t] = a;
        __syncthreads();
        float v = (shk[0][t] + shk[1][t]) + (shk[2][t] + shk[3][t]);
        // sum of squares over 128 dims (warps 0-3 hold t=0..127 when g==0)
        float ss = v * v;
        for (int o = 16; o; o >>= 1) ss += __shfl_xor_sync(0xffffffff, ss, o);
        if (g == 0 && (t & 31) == 0) red[t >> 5] = ss;
        __syncthreads();
        float tot = red[0] + red[1] + red[2] + red[3];
        float rs = rsqrtf(tot * (1.f / HDIM) + 1e-6f);
        float nv = v * rs * wqn[t] * scale;
        if (g == 0) nsh[t] = nv;
        __syncthreads();
        if (g == 0) {
            float partner = (t < 64) ? -nsh[t + 64] : nsh[t - 64];
            qout[b * HH * HDIM + h * HDIM + t] = nv * cq[t] + partner * sq[t];
        }
    } else {
        int j = blk - BB * HH;
        int b = j / KVH, kh = j % KVH;
        const float* Pk = part + b * 2560 + 2048 + kh * HDIM + t;
        const float* Pv = part + b * 2560 + 2304 + kh * HDIM + t;
        float ak = 0.f, av = 0.f;
        for (int s = g; s < S; s += 4) { ak += Pk[s * STR]; av += Pv[s * STR]; }
        shk[g][t] = ak;
        shv[g][t] = av;
        __syncthreads();
        float v  = (shk[0][t] + shk[1][t]) + (shk[2][t] + shk[3][t]);
        float vv = (shv[0][t] + shv[1][t]) + (shv[2][t] + shv[3][t]);
        float ss = v * v;
        for (int o = 16; o; o >>= 1) ss += __shfl_xor_sync(0xffffffff, ss, o);
        if (g == 0 && (t & 31) == 0) red[t >> 5] = ss;
        __syncthreads();
        float tot = red[0] + red[1] + red[2] + red[3];
        float rs = rsqrtf(tot * (1.f / HDIM) + 1e-6f);
        float nv = v * rs * wkn[t] * scale;
        if (g == 0) nsh[t] = nv;
        __syncthreads();
        if (g == 0) {
            float partner = (t < 64) ? -nsh[t + 64] : nsh[t - 64];
            float kval = nv * ck[t] + partner * sk[t];
            size_t kb = ((size_t)(l * BB + b) * KVH + kh) * (size_t)HDIM * TT;
            kcache[kb + (size_t)t * TT + TPAST] = kval;
            size_t vb = ((size_t)(l * BB + b) * KVH + kh) * (size_t)TT * HDIM;
            vcache[vb + (size_t)TPAST * HDIM + t] = vv;
        }
    }
}

// ---------------- flash-decode attention partial, cp.async overlapped ----------------
__global__ __launch_bounds__(256) void k_attn_part(
        const float* __restrict__ q, const float* __restrict__ kc,
        const float* __restrict__ vc, const float* __restrict__ ascale_p,
        float* __restrict__ po, int l) {
    extern __shared__ float smem[];
    float4* Kt = (float4*)smem;                  // 2048 f4
    float4* Vt = (float4*)(smem + CT * HDIM);    // 2048 f4
    float* qs  = smem + 2 * CT * HDIM;           // 1024
    float* ps  = qs + GQ * HDIM;                 // 512
    int tid = threadIdx.x;
    int c = blockIdx.x;
    int by = blockIdx.y;
    int b = by / KVH, kh = by % KVH;
    int t0 = c * CT;
    float madd = -128.f * ascale_p[0];

    {
        const float4* Ks = (const float4*)(kc +
            (((size_t)(l * BB + b) * KVH + kh) * HDIM) * TT + t0);
#pragma unroll
        for (int it = 0; it < HDIM * CT / 4 / 256; ++it) {
            int i = it * 256 + tid;
            int row = i >> 4, col = i & 15;
            CPA16(Kt + i, Ks + (size_t)row * (TT / 4) + col);
        }
    }
    asm volatile("cp.async.commit_group;\n");

    {
        float4 v = *(const float4*)(q + b * HH * HDIM + kh * GQ * HDIM + tid * 4);
        *(float4*)(qs + tid * 4) = v;
    }

    {
        const float4* Vs = (const float4*)(vc +
            ((size_t)(l * BB + b) * KVH + kh) * (size_t)TT * HDIM + (size_t)t0 * HDIM);
#pragma unroll
        for (int it = 0; it < CT * HDIM / 4 / 256; ++it) {
            int i = it * 256 + tid;
            CPA16(Vt + i, Vs + i);
        }
    }
    asm volatile("cp.async.commit_group;\n");

    asm volatile("cp.async.wait_group 1;\n");
    __syncthreads();

    {
        int t = tid & 63, hg = tid >> 6;
        const float* tileK = (const float*)Kt;
        float a0 = 0.f, a1 = 0.f;
        const float* q0 = qs + (hg * 2) * HDIM;
        const float* q1 = qs + (hg * 2 + 1) * HDIM;
        for (int d = 0; d < HDIM; ++d) {
            float kv = tileK[d * CT + t];
            a0 += kv * q0[d];
            a1 += kv * q1[d];
        }
        float mk = (t0 + t > 0) ? madd : 0.f;
        ps[(hg * 2) * CT + t] = a0 + mk;
        ps[(hg * 2 + 1) * CT + t] = a1 + mk;
    }
    __syncthreads();

    {
        int w = tid >> 5, lane = tid & 31;
        float e0 = ps[w * CT + lane], e1 = ps[w * CT + lane + 32];
        float mx = fmaxf(e0, e1);
        for (int o = 16; o; o >>= 1) mx = fmaxf(mx, __shfl_xor_sync(0xffffffff, mx, o));
        e0 = __expf(e0 - mx); e1 = __expf(e1 - mx);
        ps[w * CT + lane] = e0; ps[w * CT + lane + 32] = e1;
        float sum = e0 + e1;
        for (int o = 16; o; o >>= 1) sum += __shfl_xor_sync(0xffffffff, sum, o);
        if (lane == 0) {
            float* rec = po + ((size_t)by * NCH + c) * CS;
            rec[GQ * HDIM + w] = mx;
            rec[GQ * HDIM + GQ + w] = sum;
        }
    }

    asm volatile("cp.async.wait_group 0;\n");
    __syncthreads();

    {
        int d = tid & 127, hb = tid >> 7;
        const float* tileV = (const float*)Vt;
        float o[4] = {0.f, 0.f, 0.f, 0.f};
        for (int t = 0; t < CT; ++t) {
            float vv = tileV[t * HDIM + d];
#pragma unroll
            for (int g2 = 0; g2 < 4; ++g2)
                o[g2] += vv * ps[(hb * 4 + g2) * CT + t];
        }
        float* rec = po + ((size_t)by * NCH + c) * CS;
#pragma unroll
        for (int g2 = 0; g2 < 4; ++g2)
            rec[(hb * 4 + g2) * HDIM + d] = o[g2];
    }
}

// ---------------- combine attention chunks ----------------
__global__ void k_attn_fin(const float* __restrict__ po, float* __restrict__ out) {
    int b = blockIdx.x / HH, h = blockIdx.x % HH;
    int kh = h >> 3, g = h & 7;
    int tid = threadIdx.x;
    const float* base = po + (size_t)(b * KVH + kh) * NCH * CS;
    float m = -1e30f;
    for (int c = 0; c < NCH; ++c) m = fmaxf(m, base[c * CS + GQ * HDIM + g]);
    float den = 0.f, acc = 0.f;
    for (int c = 0; c < NCH; ++c) {
        float mc = base[c * CS + GQ * HDIM + g];
        float lc = base[c * CS + GQ * HDIM + GQ + g];
        float w = __expf(mc - m);
        den += lc * w;
        acc += base[c * CS + g * HDIM + tid] * w;
    }
    out[b * HH * HDIM + h * HDIM + tid] = acc / den;
}

// ---------------- past-cache copies (merged, kernel path) ----------------
#define KROWS (NL * BB * KVH * HDIM)
#define VPER  (TPAST * HDIM / 4)
#define VBLKS ((NL * BB * KVH * VPER + 255) / 256)
__global__ void k_copy_kv(const float* __restrict__ pk, float* __restrict__ outk,
                          const float4* __restrict__ pv, float4* __restrict__ outv) {
    int blk = blockIdx.x;
    if (blk < KROWS) {
        const float* src = pk + (size_t)blk * TPAST;
        float* dst = outk + (size_t)blk * TT;
        int t = threadIdx.x;
#pragma unroll 4
        for (int i = 0; i < 16; ++i) {
            int idx = i * 256 + t;
            if (idx < TPAST) dst[idx] = __ldg(src + idx);
        }
    } else {
        long long i = (long long)(blk - KROWS) * 256 + threadIdx.x;
        if (i < (long long)NL * BB * KVH * VPER) {
            int ch = (int)(i / VPER);
            int rem = (int)(i - (long long)ch * VPER);
            outv[(size_t)ch * (TT * HDIM / 4) + rem] = __ldg(pv + (size_t)ch * VPER + rem);
        }
    }
}

// ---------------- host ----------------
#define GEMV_SMEM(DC) (98304 + BB * (DC) * 8)
#define ATTN_SMEM ((2 * CT * HDIM + GQ * HDIM + GQ * CT) * 4)

extern "C" void kernel_launch(void* const* d_in, const int* in_sizes, int n_in,
                              void* d_out, int out_size) {
    const float* hid   = (const float*)d_in[0];
    const float* pastk = (const float*)d_in[1];
    const float* pastv = (const float*)d_in[2];
    const float* deeps = (const float*)d_in[3];
    const float* cosq  = (const float*)d_in[4];
    const float* sinq  = (const float*)d_in[5];
    const float* cosk  = (const float*)d_in[6];
    const float* sink  = (const float*)d_in[7];
    const float* ascl  = (const float*)d_in[8];
    const float* w_in  = (const float*)d_in[9];
    const float* wq    = (const float*)d_in[10];
    const float* wk    = (const float*)d_in[11];
    const float* wv    = (const float*)d_in[12];
    const float* wqn   = (const float*)d_in[13];
    const float* wkn   = (const float*)d_in[14];
    const float* wo    = (const float*)d_in[15];
    const float* wpost = (const float*)d_in[16];
    const float* wgate = (const float*)d_in[17];
    const float* wup   = (const float*)d_in[18];
    const float* wdown = (const float*)d_in[19];
    const float* wfin  = (const float*)d_in[20];
    const float* wlm   = (const float*)d_in[21];

    float* out  = (float*)d_out;
    float* outk = out + BB * VV;
    float* outv = outk + (size_t)NL * BB * KVH * HDIM * TT;

    static float* sp = nullptr;
    if (!sp) {
        cudaGetSymbolAddress((void**)&sp, g_scratch);
        cudaFuncSetAttribute(k_attn_part, cudaFuncAttributeMaxDynamicSharedMemorySize,
                             ATTN_SMEM);
        cudaFuncSetAttribute(k_gemv_cp<64>,  cudaFuncAttributeMaxDynamicSharedMemorySize, GEMV_SMEM(64));
        cudaFuncSetAttribute(k_gemv_cp<128>, cudaFuncAttributeMaxDynamicSharedMemorySize, GEMV_SMEM(128));
        cudaFuncSetAttribute(k_gemv_cp<192>, cudaFuncAttributeMaxDynamicSharedMemorySize, GEMV_SMEM(192));
        cudaFuncSetAttribute(k_gemv_cp<512>, cudaFuncAttributeMaxDynamicSharedMemorySize, GEMV_SMEM(512));
    }
    float* g_h     = sp;
    float* g_hn    = sp + 6144;
    float* g_q     = sp + 19968;
    float* g_attn  = sp + 26112;
    float* g_gu    = sp + 32256;
    float* g_apart = sp + 69120;     // BB*KVH*NCH*CS = 399360 floats
    float* g_part  = sp + 468480;

    k_copy_kv<<<KROWS + VBLKS, 256>>>(pastk, outk, (const float4*)pastv, (float4*)outv);

    const float* hptr = hid;
    for (int l = 0; l < NL; ++l) {
        k_rmsnorm<<<BB, 256>>>(hptr, w_in + l * DD, g_hn);
        // QKV: 640 f4 cols -> 5 tiles; 32 splits of 64 (reduce fused into rope)
        k_gemv_cp<64><<<dim3(5, 32), 128, GEMV_SMEM(64)>>>(g_hn, nullptr, nullptr, DD,
            wq + (size_t)l * DD * 2048, 2048,
            wk + (size_t)l * DD * 256, 256,
            wv + (size_t)l * DD * 256, 256, 2560, g_part);

        k_rope<<<BB * HH + BB * KVH, 512>>>(g_part, 32, wqn + l * HDIM, wkn + l * HDIM,
                                            cosq, sinq, cosk, sink,
                                            g_q, outk, outv, l);

        k_attn_part<<<dim3(NCH, BB * KVH), 256, ATTN_SMEM>>>(g_q, outk, outv, ascl,
                                                             g_apart, l);
        k_attn_fin<<<BB * HH, 128>>>(g_apart, g_attn);

        // wo: 512 f4 -> 4 tiles; 32 splits of 64
        k_gemv_cp<64><<<dim3(4, 32), 128, GEMV_SMEM(64)>>>(g_attn, nullptr, nullptr, DD,
            wo + (size_t)l * DD * DD, DD, nullptr, 0, nullptr, 0, DD, g_part);
        k_reduce<<<24, 256>>>(g_part, 32, DD, hptr, nullptr, g_h);

        k_rmsnorm<<<BB, 256>>>(g_h, wpost + l * DD, g_hn);
        // gate|up: 3072 f4 -> 24 tiles; 16 splits of 128
        k_gemv_cp<128><<<dim3(24, 16), 128, GEMV_SMEM(128)>>>(g_hn, nullptr, nullptr, DD,
            wgate + (size_t)l * DD * FF, FF,
            wup + (size_t)l * DD * FF, FF,
            nullptr, 0, 2 * FF, g_part);
        k_reduce<<<144, 256>>>(g_part, 16, 2 * FF, nullptr, nullptr, g_gu);

        // down (fused silu*up): 512 f4 -> 4 tiles; 32 splits of 192 over D=6144
        k_gemv_cp<192><<<dim3(4, 32), 128, GEMV_SMEM(192)>>>(nullptr, g_gu, g_gu + FF, 2 * FF,
            wdown + (size_t)l * FF * DD, DD, nullptr, 0, nullptr, 0, DD, g_part);
        const float* ds = (l < 3) ? (deeps + (size_t)l * BB * DD) : nullptr;
        k_reduce<<<24, 256>>>(g_part, 32, DD, g_h, ds, g_h);
        hptr = g_h;
    }

    k_rmsnorm<<<BB, 256>>>(g_h, wfin, g_hn);
    // lm_head: 8000 f4 -> 63 tiles; 4 splits of 512
    k_gemv_cp<512><<<dim3(63, 4), 128, GEMV_SMEM(512)>>>(g_hn, nullptr, nullptr, DD,
        wlm, VV, nullptr, 0, nullptr, 0, VV, g_part);
    k_reduce<<<375, 256>>>(g_part, 4, VV, nullptr, nullptr, out);
}

// round 17
// speedup vs baseline: 1.3240x; 1.0056x over previous
#include <cuda_runtime.h>
#include <cuda_bf16.h>
#include <cstdint>
#include <cstddef>

#define BB 3
#define DD 2048
#define HH 16
#define HDIM 128
#define KVH 2
#define FF 6144
#define VV 32000
#define TT 4096
#define TPAST 4095
#define NL 4
#define GQ (HH / KVH)   // 8
#define NCH 64          // attention chunks over T
#define CT 64           // tokens per chunk
#define CS (GQ * HDIM + 2 * GQ)   // 1040

__device__ float g_scratch[468480 + 1400000];

__device__ __forceinline__ uint32_t smem_u32(const void* p) {
    return (uint32_t)__cvta_generic_to_shared(p);
}
#define FMA2(acc, w, x) \
    asm("fma.rn.f32x2 %0, %1, %2, %0;" : "+l"(acc) : "l"(w), "l"(x))
#define PACK2(out, lo, hi) \
    asm("mov.b64 %0, {%1, %2};" : "=l"(out) : "f"(lo), "f"(hi))
#define UNPACK2(lo, hi, in) \
    asm("mov.b64 {%0, %1}, %2;" : "=f"(lo), "=f"(hi) : "l"(in))
#define CPA16(dst, src) \
    asm volatile("cp.async.cg.shared.global [%0], [%1], 16;\n" \
                 :: "r"(smem_u32(dst)), "l"(src))

// ---------------- rmsnorm ----------------
__global__ void k_rmsnorm(const float* __restrict__ x, const float* __restrict__ w,
                          float* __restrict__ y) {
    int b = blockIdx.x;
    const float* xb = x + b * DD;
    __shared__ float red[256];
    float ss = 0.f;
    for (int i = threadIdx.x; i < DD; i += 256) { float v = xb[i]; ss += v * v; }
    red[threadIdx.x] = ss;
    __syncthreads();
    for (int s = 128; s > 0; s >>= 1) {
        if (threadIdx.x < s) red[threadIdx.x] += red[threadIdx.x + s];
        __syncthreads();
    }
    float rs = rsqrtf(red[0] * (1.f / DD) + 1e-6f);
    for (int i = threadIdx.x; i < DD; i += 256) y[b * DD + i] = xb[i] * rs * w[i];
}

// ---------------- split-K GEMV, cp.async 6-stage ring + packed f32x2 math ----------------
template <int DC>
__global__ __launch_bounds__(128) void k_gemv_cp(
        const float* __restrict__ x,
        const float* __restrict__ xg, const float* __restrict__ xu, int xstride,
        const float* __restrict__ W0, int n0,
        const float* __restrict__ W1, int n1,
        const float* __restrict__ W2, int n2,
        int Ntot, float* __restrict__ part) {
    constexpr int SR = 8;
    constexpr int NS = 6;
    constexpr int STAGES = DC / SR;
    extern __shared__ float4 sm4[];
    float4* wt = sm4;                                           // [NS][SR][128] f4
    unsigned long long* xq = (unsigned long long*)(sm4 + NS * SR * 128); // [BB][DC] {v,v}

    int tid = threadIdx.x;
    int d0 = blockIdx.y * DC;
    int c4 = blockIdx.x * 128 + tid;
    int n = c4 * 4;
    bool active = n < Ntot;

    const float4* Wr = nullptr;
    size_t ld4 = 0;
    if (active) {
        const float* Wp; int c, ld;
        if (n < n0)            { Wp = W0; c = n;           ld = n0; }
        else if (n < n0 + n1)  { Wp = W1; c = n - n0;      ld = n1; }
        else                   { Wp = W2; c = n - n0 - n1; ld = n2; }
        Wr = reinterpret_cast<const float4*>(Wp + (size_t)d0 * ld) + (c >> 2);
        ld4 = (size_t)(ld >> 2);
    }

#pragma unroll
    for (int s = 0; s < NS - 1; ++s) {
        if (active) {
            float4* dst = wt + (s * SR) * 128 + tid;
            const float4* src = Wr + (size_t)(s * SR) * ld4;
#pragma unroll
            for (int r = 0; r < SR; ++r)
                CPA16(dst + r * 128, src + r * ld4);
        }
        asm volatile("cp.async.commit_group;\n");
    }

    for (int i = tid; i < BB * DC; i += 128) {
        int b = i / DC, d = i - b * DC;
        float v;
        if (xg) {
            float g = xg[b * xstride + d0 + d];
            float u = xu[b * xstride + d0 + d];
            v = (g / (1.f + __expf(-g))) * u;
        } else {
            v = x[b * xstride + d0 + d];
        }
        unsigned long long p;
        PACK2(p, v, v);
        xq[i] = p;
    }
    __syncthreads();

    unsigned long long a0l = 0, a0h = 0, a1l = 0, a1h = 0, a2l = 0, a2h = 0;
    const ulonglong2* wt64 = (const ulonglong2*)wt;
    for (int s = 0; s < STAGES; ++s) {
        int sn = s + NS - 1;
        if (sn < STAGES && active) {
            float4* dst = wt + ((sn % NS) * SR) * 128 + tid;
            const float4* src = Wr + (size_t)(sn * SR) * ld4;
#pragma unroll
            for (int r = 0; r < SR; ++r)
                CPA16(dst + r * 128, src + r * ld4);
        }
        asm volatile("cp.async.commit_group;\n");
        asm volatile("cp.async.wait_group 5;\n");
        int buf = s % NS;
        if (active) {
#pragma unroll
            for (int r = 0; r < SR; ++r) {
                ulonglong2 wv = wt64[(buf * SR + r) * 128 + tid];
                int d = s * SR + r;
                unsigned long long xx0 = xq[d];
                unsigned long long xx1 = xq[DC + d];
                unsigned long long xx2 = xq[2 * DC + d];
                FMA2(a0l, wv.x, xx0); FMA2(a0h, wv.y, xx0);
                FMA2(a1l, wv.x, xx1); FMA2(a1h, wv.y, xx1);
                FMA2(a2l, wv.x, xx2); FMA2(a2h, wv.y, xx2);
            }
        }
    }
    if (active) {
        float4 a0, a1, a2;
        UNPACK2(a0.x, a0.y, a0l); UNPACK2(a0.z, a0.w, a0h);
        UNPACK2(a1.x, a1.y, a1l); UNPACK2(a1.z, a1.w, a1h);
        UNPACK2(a2.x, a2.y, a2l); UNPACK2(a2.z, a2.w, a2h);
        float* P = part + (size_t)blockIdx.y * BB * Ntot;
        *(float4*)(P + 0 * (size_t)Ntot + n) = a0;
        *(float4*)(P + 1 * (size_t)Ntot + n) = a1;
        *(float4*)(P + 2 * (size_t)Ntot + n) = a2;
    }
}

// ---------------- reduce: 4 thread-groups over splits, smem combine ----------------
__global__ void k_reduce(const float* __restrict__ part, int S, int Ntot,
                         const float* __restrict__ r1, const float* __restrict__ r2,
                         float* __restrict__ y) {
    __shared__ float4 sh[4][64];
    int sg = threadIdx.x >> 6;        // split group 0..3
    int t  = threadIdx.x & 63;
    int tot4 = BB * Ntot / 4;
    const float4* P4 = (const float4*)part;
    for (int base = blockIdx.x * 64; base < tot4; base += gridDim.x * 64) {
        int i = base + t;
        float4 a = {0, 0, 0, 0};
        if (i < tot4) {
            for (int s = sg; s < S; s += 4) {
                float4 p = P4[(size_t)s * tot4 + i];
                a.x += p.x; a.y += p.y; a.z += p.z; a.w += p.w;
            }
        }
        sh[sg][t] = a;
        __syncthreads();
        if (sg == 0 && i < tot4) {
            float4 b1 = sh[1][t], b2 = sh[2][t], b3 = sh[3][t];
            a.x = (a.x + b1.x) + (b2.x + b3.x);
            a.y = (a.y + b1.y) + (b2.y + b3.y);
            a.z = (a.z + b1.z) + (b2.z + b3.z);
            a.w = (a.w + b1.w) + (b2.w + b3.w);
            if (r1) { float4 r = ((const float4*)r1)[i]; a.x += r.x; a.y += r.y; a.z += r.z; a.w += r.w; }
            if (r2) { float4 r = ((const float4*)r2)[i]; a.x += r.x; a.y += r.y; a.z += r.z; a.w += r.w; }
            ((float4*)y)[i] = a;
        }
        __syncthreads();
    }
}

// ---------------- per-head RMSNorm + RoPE, fused QKV reduction (8 thread-groups) ----------------
__global__ __launch_bounds__(1024) void k_rope(
        const float* __restrict__ part, int S,
        const float* __restrict__ wqn, const float* __restrict__ wkn,
        const float* __restrict__ cq, const float* __restrict__ sq,
        const float* __restrict__ ck, const float* __restrict__ sk,
        float* __restrict__ qout, float* __restrict__ kcache,
        float* __restrict__ vcache, int l) {
    __shared__ float shk[8][HDIM];
    __shared__ float shv[8][HDIM];
    __shared__ float nsh[HDIM];
    __shared__ float red[4];
    int tid = threadIdx.x;
    int g = tid >> 7, t = tid & 127;
    int blk = blockIdx.x;
    const float scale = 0.29730177875068026f;  // 128^-0.25
    const size_t STR = (size_t)BB * 2560;

    if (blk < BB * HH) {
        int b = blk / HH, h = blk % HH;
        const float* P = part + b * 2560 + h * HDIM + t;
        float a = 0.f;
        for (int s = g; s < S; s += 8) a += P[s * STR];
        shk[g][t] = a;
        __syncthreads();
        float v = ((shk[0][t] + shk[1][t]) + (shk[2][t] + shk[3][t]))
                + ((shk[4][t] + shk[5][t]) + (shk[6][t] + shk[7][t]));
        float ss = v * v;
        for (int o = 16; o; o >>= 1) ss += __shfl_xor_sync(0xffffffff, ss, o);
        if (g == 0 && (t & 31) == 0) red[t >> 5] = ss;
        __syncthreads();
        float tot = red[0] + red[1] + red[2] + red[3];
        float rs = rsqrtf(tot * (1.f / HDIM) + 1e-6f);
        float nv = v * rs * wqn[t] * scale;
        if (g == 0) nsh[t] = nv;
        __syncthreads();
        if (g == 0) {
            float partner = (t < 64) ? -nsh[t + 64] : nsh[t - 64];
            qout[b * HH * HDIM + h * HDIM + t] = nv * cq[t] + partner * sq[t];
        }
    } else {
        int j = blk - BB * HH;
        int b = j / KVH, kh = j % KVH;
        const float* Pk = part + b * 2560 + 2048 + kh * HDIM + t;
        const float* Pv = part + b * 2560 + 2304 + kh * HDIM + t;
        float ak = 0.f, av = 0.f;
        for (int s = g; s < S; s += 8) { ak += Pk[s * STR]; av += Pv[s * STR]; }
        shk[g][t] = ak;
        shv[g][t] = av;
        __syncthreads();
        float v  = ((shk[0][t] + shk[1][t]) + (shk[2][t] + shk[3][t]))
                 + ((shk[4][t] + shk[5][t]) + (shk[6][t] + shk[7][t]));
        float vv = ((shv[0][t] + shv[1][t]) + (shv[2][t] + shv[3][t]))
                 + ((shv[4][t] + shv[5][t]) + (shv[6][t] + shv[7][t]));
        float ss = v * v;
        for (int o = 16; o; o >>= 1) ss += __shfl_xor_sync(0xffffffff, ss, o);
        if (g == 0 && (t & 31) == 0) red[t >> 5] = ss;
        __syncthreads();
        float tot = red[0] + red[1] + red[2] + red[3];
        float rs = rsqrtf(tot * (1.f / HDIM) + 1e-6f);
        float nv = v * rs * wkn[t] * scale;
        if (g == 0) nsh[t] = nv;
        __syncthreads();
        if (g == 0) {
            float partner = (t < 64) ? -nsh[t + 64] : nsh[t - 64];
            float kval = nv * ck[t] + partner * sk[t];
            size_t kb = ((size_t)(l * BB + b) * KVH + kh) * (size_t)HDIM * TT;
            kcache[kb + (size_t)t * TT + TPAST] = kval;
            size_t vb = ((size_t)(l * BB + b) * KVH + kh) * (size_t)TT * HDIM;
            vcache[vb + (size_t)TPAST * HDIM + t] = vv;
        }
    }
}

// ---------------- flash-decode attention partial, cp.async overlapped ----------------
__global__ __launch_bounds__(256) void k_attn_part(
        const float* __restrict__ q, const float* __restrict__ kc,
        const float* __restrict__ vc, const float* __restrict__ ascale_p,
        float* __restrict__ po, int l) {
    extern __shared__ float smem[];
    float4* Kt = (float4*)smem;
    float4* Vt = (float4*)(smem + CT * HDIM);
    float* qs  = smem + 2 * CT * HDIM;
    float* ps  = qs + GQ * HDIM;
    int tid = threadIdx.x;
    int c = blockIdx.x;
    int by = blockIdx.y;
    int b = by / KVH, kh = by % KVH;
    int t0 = c * CT;
    float madd = -128.f * ascale_p[0];

    {
        const float4* Ks = (const float4*)(kc +
            (((size_t)(l * BB + b) * KVH + kh) * HDIM) * TT + t0);
#pragma unroll
        for (int it = 0; it < HDIM * CT / 4 / 256; ++it) {
            int i = it * 256 + tid;
            int row = i >> 4, col = i & 15;
            CPA16(Kt + i, Ks + (size_t)row * (TT / 4) + col);
        }
    }
    asm volatile("cp.async.commit_group;\n");

    {
        float4 v = *(const float4*)(q + b * HH * HDIM + kh * GQ * HDIM + tid * 4);
        *(float4*)(qs + tid * 4) = v;
    }

    {
        const float4* Vs = (const float4*)(vc +
            ((size_t)(l * BB + b) * KVH + kh) * (size_t)TT * HDIM + (size_t)t0 * HDIM);
#pragma unroll
        for (int it = 0; it < CT * HDIM / 4 / 256; ++it) {
            int i = it * 256 + tid;
            CPA16(Vt + i, Vs + i);
        }
    }
    asm volatile("cp.async.commit_group;\n");

    asm volatile("cp.async.wait_group 1;\n");
    __syncthreads();

    {
        int t = tid & 63, hg = tid >> 6;
        const float* tileK = (const float*)Kt;
        float a0 = 0.f, a1 = 0.f;
        const float* q0 = qs + (hg * 2) * HDIM;
        const float* q1 = qs + (hg * 2 + 1) * HDIM;
        for (int d = 0; d < HDIM; ++d) {
            float kv = tileK[d * CT + t];
            a0 += kv * q0[d];
            a1 += kv * q1[d];
        }
        float mk = (t0 + t > 0) ? madd : 0.f;
        ps[(hg * 2) * CT + t] = a0 + mk;
        ps[(hg * 2 + 1) * CT + t] = a1 + mk;
    }
    __syncthreads();

    {
        int w = tid >> 5, lane = tid & 31;
        float e0 = ps[w * CT + lane], e1 = ps[w * CT + lane + 32];
        float mx = fmaxf(e0, e1);
        for (int o = 16; o; o >>= 1) mx = fmaxf(mx, __shfl_xor_sync(0xffffffff, mx, o));
        e0 = __expf(e0 - mx); e1 = __expf(e1 - mx);
        ps[w * CT + lane] = e0; ps[w * CT + lane + 32] = e1;
        float sum = e0 + e1;
        for (int o = 16; o; o >>= 1) sum += __shfl_xor_sync(0xffffffff, sum, o);
        if (lane == 0) {
            float* rec = po + ((size_t)by * NCH + c) * CS;
            rec[GQ * HDIM + w] = mx;
            rec[GQ * HDIM + GQ + w] = sum;
        }
    }

    asm volatile("cp.async.wait_group 0;\n");
    __syncthreads();

    {
        int d = tid & 127, hb = tid >> 7;
        const float* tileV = (const float*)Vt;
        float o[4] = {0.f, 0.f, 0.f, 0.f};
        for (int t = 0; t < CT; ++t) {
            float vv = tileV[t * HDIM + d];
#pragma unroll
            for (int g2 = 0; g2 < 4; ++g2)
                o[g2] += vv * ps[(hb * 4 + g2) * CT + t];
        }
        float* rec = po + ((size_t)by * NCH + c) * CS;
#pragma unroll
        for (int g2 = 0; g2 < 4; ++g2)
            rec[(hb * 4 + g2) * HDIM + d] = o[g2];
    }
}

// ---------------- combine attention chunks ----------------
__global__ void k_attn_fin(const float* __restrict__ po, float* __restrict__ out) {
    int b = blockIdx.x / HH, h = blockIdx.x % HH;
    int kh = h >> 3, g = h & 7;
    int tid = threadIdx.x;
    const float* base = po + (size_t)(b * KVH + kh) * NCH * CS;
    float m = -1e30f;
    for (int c = 0; c < NCH; ++c) m = fmaxf(m, base[c * CS + GQ * HDIM + g]);
    float den = 0.f, acc = 0.f;
    for (int c = 0; c < NCH; ++c) {
        float mc = base[c * CS + GQ * HDIM + g];
        float lc = base[c * CS + GQ * HDIM + GQ + g];
        float w = __expf(mc - m);
        den += lc * w;
        acc += base[c * CS + g * HDIM + tid] * w;
    }
    out[b * HH * HDIM + h * HDIM + tid] = acc / den;
}

// ---------------- past-cache copies: scalar loads + float4 stores for K ----------------
#define KROWS (NL * BB * KVH * HDIM)             // 12288 K rows
#define VPER  (TPAST * HDIM / 4)                 // 131040 float4 per (l,b,kh)
#define VBLKS ((NL * BB * KVH * VPER + 255) / 256)
__global__ void k_copy_kv(const float* __restrict__ pk, float* __restrict__ outk,
                          const float4* __restrict__ pv, float4* __restrict__ outv) {
    int blk = blockIdx.x;
    if (blk < KROWS) {
        const float* src = pk + (size_t)blk * TPAST;
        float* dst = outk + (size_t)blk * TT;      // 16B-aligned rows
        int t = threadIdx.x;
        // 1023 float4 stores (4092 floats), scalar loads
#pragma unroll 4
        for (int i = 0; i < 4; ++i) {
            int idx = i * 256 + t;
            if (idx < 1023) {
                float a = __ldg(src + idx * 4 + 0);
                float b = __ldg(src + idx * 4 + 1);
                float c = __ldg(src + idx * 4 + 2);
                float d = __ldg(src + idx * 4 + 3);
                float4 v = {a, b, c, d};
                *(float4*)(dst + idx * 4) = v;
            }
        }
        if (t < 3) dst[4092 + t] = __ldg(src + 4092 + t);
    } else {
        long long i = (long long)(blk - KROWS) * 256 + threadIdx.x;
        if (i < (long long)NL * BB * KVH * VPER) {
            int ch = (int)(i / VPER);
            int rem = (int)(i - (long long)ch * VPER);
            outv[(size_t)ch * (TT * HDIM / 4) + rem] = __ldg(pv + (size_t)ch * VPER + rem);
        }
    }
}

// ---------------- host ----------------
#define GEMV_SMEM(DC) (98304 + BB * (DC) * 8)
#define ATTN_SMEM ((2 * CT * HDIM + GQ * HDIM + GQ * CT) * 4)

extern "C" void kernel_launch(void* const* d_in, const int* in_sizes, int n_in,
                              void* d_out, int out_size) {
    const float* hid   = (const float*)d_in[0];
    const float* pastk = (const float*)d_in[1];
    const float* pastv = (const float*)d_in[2];
    const float* deeps = (const float*)d_in[3];
    const float* cosq  = (const float*)d_in[4];
    const float* sinq  = (const float*)d_in[5];
    const float* cosk  = (const float*)d_in[6];
    const float* sink  = (const float*)d_in[7];
    const float* ascl  = (const float*)d_in[8];
    const float* w_in  = (const float*)d_in[9];
    const float* wq    = (const float*)d_in[10];
    const float* wk    = (const float*)d_in[11];
    const float* wv    = (const float*)d_in[12];
    const float* wqn   = (const float*)d_in[13];
    const float* wkn   = (const float*)d_in[14];
    const float* wo    = (const float*)d_in[15];
    const float* wpost = (const float*)d_in[16];
    const float* wgate = (const float*)d_in[17];
    const float* wup   = (const float*)d_in[18];
    const float* wdown = (const float*)d_in[19];
    const float* wfin  = (const float*)d_in[20];
    const float* wlm   = (const float*)d_in[21];

    float* out  = (float*)d_out;
    float* outk = out + BB * VV;
    float* outv = outk + (size_t)NL * BB * KVH * HDIM * TT;

    static float* sp = nullptr;
    if (!sp) {
        cudaGetSymbolAddress((void**)&sp, g_scratch);
        cudaFuncSetAttribute(k_attn_part, cudaFuncAttributeMaxDynamicSharedMemorySize,
                             ATTN_SMEM);
        cudaFuncSetAttribute(k_gemv_cp<64>,  cudaFuncAttributeMaxDynamicSharedMemorySize, GEMV_SMEM(64));
        cudaFuncSetAttribute(k_gemv_cp<128>, cudaFuncAttributeMaxDynamicSharedMemorySize, GEMV_SMEM(128));
        cudaFuncSetAttribute(k_gemv_cp<192>, cudaFuncAttributeMaxDynamicSharedMemorySize, GEMV_SMEM(192));
        cudaFuncSetAttribute(k_gemv_cp<512>, cudaFuncAttributeMaxDynamicSharedMemorySize, GEMV_SMEM(512));
    }
    float* g_h     = sp;
    float* g_hn    = sp + 6144;
    float* g_q     = sp + 19968;
    float* g_attn  = sp + 26112;
    float* g_gu    = sp + 32256;
    float* g_apart = sp + 69120;     // BB*KVH*NCH*CS = 399360 floats
    float* g_part  = sp + 468480;

    k_copy_kv<<<KROWS + VBLKS, 256>>>(pastk, outk, (const float4*)pastv, (float4*)outv);

    const float* hptr = hid;
    for (int l = 0; l < NL; ++l) {
        k_rmsnorm<<<BB, 256>>>(hptr, w_in + l * DD, g_hn);
        // QKV: 640 f4 cols -> 5 tiles; 32 splits of 64 (reduce fused into rope)
        k_gemv_cp<64><<<dim3(5, 32), 128, GEMV_SMEM(64)>>>(g_hn, nullptr, nullptr, DD,
            wq + (size_t)l * DD * 2048, 2048,
            wk + (size_t)l * DD * 256, 256,
            wv + (size_t)l * DD * 256, 256, 2560, g_part);

        k_rope<<<BB * HH + BB * KVH, 1024>>>(g_part, 32, wqn + l * HDIM, wkn + l * HDIM,
                                             cosq, sinq, cosk, sink,
                                             g_q, outk, outv, l);

        k_attn_part<<<dim3(NCH, BB * KVH), 256, ATTN_SMEM>>>(g_q, outk, outv, ascl,
                                                             g_apart, l);
        k_attn_fin<<<BB * HH, 128>>>(g_apart, g_attn);

        // wo: 512 f4 -> 4 tiles; 32 splits of 64
        k_gemv_cp<64><<<dim3(4, 32), 128, GEMV_SMEM(64)>>>(g_attn, nullptr, nullptr, DD,
            wo + (size_t)l * DD * DD, DD, nullptr, 0, nullptr, 0, DD, g_part);
        k_reduce<<<24, 256>>>(g_part, 32, DD, hptr, nullptr, g_h);

        k_rmsnorm<<<BB, 256>>>(g_h, wpost + l * DD, g_hn);
        // gate|up: 3072 f4 -> 24 tiles; 16 splits of 128
        k_gemv_cp<128><<<dim3(24, 16), 128, GEMV_SMEM(128)>>>(g_hn, nullptr, nullptr, DD,
            wgate + (size_t)l * DD * FF, FF,
            wup + (size_t)l * DD * FF, FF,
            nullptr, 0, 2 * FF, g_part);
        k_reduce<<<144, 256>>>(g_part, 16, 2 * FF, nullptr, nullptr, g_gu);

        // down (fused silu*up): 512 f4 -> 4 tiles; 32 splits of 192 over D=6144
        k_gemv_cp<192><<<dim3(4, 32), 128, GEMV_SMEM(192)>>>(nullptr, g_gu, g_gu + FF, 2 * FF,
            wdown + (size_t)l * FF * DD, DD, nullptr, 0, nullptr, 0, DD, g_part);
        const float* ds = (l < 3) ? (deeps + (size_t)l * BB * DD) : nullptr;
        k_reduce<<<24, 256>>>(g_part, 32, DD, g_h, ds, g_h);
        hptr = g_h;
    }

    k_rmsnorm<<<BB, 256>>>(g_h, wfin, g_hn);
    // lm_head: 8000 f4 -> 63 tiles; 4 splits of 512
    k_gemv_cp<512><<<dim3(63, 4), 128, GEMV_SMEM(512)>>>(g_hn, nullptr, nullptr, DD,
        wlm, VV, nullptr, 0, nullptr, 0, VV, g_part);
    k_reduce<<<375, 256>>>(g_part, 4, VV, nullptr, nullptr, out);
}